// round 5
// baseline (speedup 1.0000x reference)
#include <cuda_runtime.h>
#include <cuda_bf16.h>

#define D 128
#define B_MAX 16384

__device__ int g_starts[B_MAX + 1];

// Streaming boundary detection over sorted index: one coalesced pass.
__global__ void bounds_kernel(const int* __restrict__ index, int n, int B) {
    int i = blockIdx.x * blockDim.x + threadIdx.x;
    if (i >= n) return;
    int b = index[i];
    int a = (i == 0) ? -1 : index[i - 1];
    for (int s = a + 1; s <= b; s++) g_starts[s] = i;
    if (i == n - 1) {
        for (int s = b + 1; s <= B; s++) g_starts[s] = n;
    }
}

__device__ __forceinline__ float fast_tanh(float v) {
    float r;
    asm("tanh.approx.f32 %0, %1;" : "=f"(r) : "f"(v));
    return r;
}

__global__ __launch_bounds__(256, 6) void seg_attn_kernel(
    const float* __restrict__ x,
    const float* __restrict__ refm,
    const float* __restrict__ W,
    const float* __restrict__ bptr,
    float*       __restrict__ out)
{
    const int s    = blockIdx.x;
    const int tid  = threadIdx.x;
    const int w    = tid >> 5;
    const int lane = tid & 31;

    __shared__ float4 stage[8][4][32];   // 16 KB: xv staging (regs -> smem)
    __shared__ float  acc_s[8][D];       // 4 KB
    __shared__ float  esum_s[8];

    const int start = g_starts[s];
    const int end   = g_starts[s + 1];

    if (start == end) {                       // empty segment -> zeros
        if (tid < D) out[(size_t)s * D + tid] = 0.0f;
        return;
    }

    // W in registers: lane owns feature columns [4*lane, 4*lane+3]
    const float4 Wa = ((const float4*)W)[lane];        // x half
    const float4 Wb = ((const float4*)W)[32 + lane];   // ref half
    const float  bb = bptr[0];

    const float* xlane = x    + (size_t)lane * 4;
    const float* rlane = refm + (size_t)lane * 4;

    float4 acc  = make_float4(0.f, 0.f, 0.f, 0.f);
    float  esum = 0.f;

    const unsigned FULL = 0xffffffffu;

    // 4 rows per warp per iteration; xv parked in smem across the reduction.
    for (int r0 = start + w * 4; r0 < end; r0 += 32) {
        float p[4];
        #pragma unroll
        for (int k = 0; k < 4; k++) {
            const int r = r0 + k;
            float4 xv = make_float4(0.f, 0.f, 0.f, 0.f);
            float4 rv = make_float4(0.f, 0.f, 0.f, 0.f);
            if (r < end) {
                xv = *(const float4*)(xlane + (size_t)r * D);
                rv = *(const float4*)(rlane + (size_t)r * D);
            }
            stage[w][k][lane] = xv;          // STS: issue-only, frees the regs
            p[k] = xv.x * Wa.x + xv.y * Wa.y + xv.z * Wa.z + xv.w * Wa.w
                 + rv.x * Wb.x + rv.y * Wb.y + rv.z * Wb.z + rv.w * Wb.w;
        }

        // Tree-merge 4-row reduction: 9 shuffles.
        float t0 = __shfl_xor_sync(FULL, p[0], 16);
        float t1 = __shfl_xor_sync(FULL, p[1], 16);
        float q0 = (lane & 16) ? (p[1] + t1) : (p[0] + t0);
        float t2 = __shfl_xor_sync(FULL, p[2], 16);
        float t3 = __shfl_xor_sync(FULL, p[3], 16);
        float q1 = (lane & 16) ? (p[3] + t3) : (p[2] + t2);
        float u0 = __shfl_xor_sync(FULL, q0, 8);
        float u1 = __shfl_xor_sync(FULL, q1, 8);
        float v  = (lane & 8) ? (q1 + u1) : (q0 + u0);
        v += __shfl_xor_sync(FULL, v, 4);
        v += __shfl_xor_sync(FULL, v, 2);
        v += __shfl_xor_sync(FULL, v, 1);
        // Row sums: lane 0 -> row0, 16 -> row1, 8 -> row2, 24 -> row3.

        // softmax shift-invariant + tanh bounded: no segment max needed.
        const float ev = __expf(fast_tanh(v + bb));
        float e[4];
        e[0] = __shfl_sync(FULL, ev, 0);
        e[1] = __shfl_sync(FULL, ev, 16);
        e[2] = __shfl_sync(FULL, ev, 8);
        e[3] = __shfl_sync(FULL, ev, 24);

        #pragma unroll
        for (int k = 0; k < 4; k++) {
            if (r0 + k < end) {
                const float4 xv = stage[w][k][lane];   // LDS, conflict-free
                esum  += e[k];
                acc.x += e[k] * xv.x;
                acc.y += e[k] * xv.y;
                acc.z += e[k] * xv.z;
                acc.w += e[k] * xv.w;
            }
        }
    }

    ((float4*)acc_s[w])[lane] = acc;
    if (lane == 0) esum_s[w] = esum;
    __syncthreads();

    if (tid < D) {
        float t = 0.f, es = 0.f;
        #pragma unroll
        for (int i = 0; i < 8; i++) { t += acc_s[i][tid]; es += esum_s[i]; }
        out[(size_t)s * D + tid] = t / (es + 1e-16f);
    }
}

extern "C" void kernel_launch(void* const* d_in, const int* in_sizes, int n_in,
                              void* d_out, int out_size) {
    // metadata order: x, ref, index, batch_size, W, b
    const float* x     = (const float*)d_in[0];
    const float* refm  = (const float*)d_in[1];
    const int*   index = (const int*)  d_in[2];
    const float* W     = (const float*)d_in[4];
    const float* b     = (const float*)d_in[5];
    float* out = (float*)d_out;

    const int n = in_sizes[0] / D;   // 500000
    const int B = out_size / D;      // 16384

    bounds_kernel<<<(n + 255) / 256, 256>>>(index, n, B);
    seg_attn_kernel<<<B, 256>>>(x, refm, W, b, out);
}

// round 6
// speedup vs baseline: 1.2971x; 1.2971x over previous
#include <cuda_runtime.h>
#include <cuda_bf16.h>

#define D 128
#define B_MAX 16384

// Unnormalized per-segment accumulators. Zero-initialized at load; every
// launch leaves them zeroed again (finalize kernel re-zeroes after reading).
__device__ float g_num[B_MAX * D];   // 8 MB
__device__ float g_esum[B_MAX];

__device__ __forceinline__ float fast_tanh(float v) {
    float r;
    asm("tanh.approx.f32 %0, %1;" : "=f"(r) : "f"(v));
    return r;
}

#define ROWS_PER_WARP 32

__global__ __launch_bounds__(256) void logits_accum_kernel(
    const float* __restrict__ x,
    const float* __restrict__ refm,
    const int*   __restrict__ index,
    const float* __restrict__ W,
    const float* __restrict__ bptr,
    int n)
{
    const int tid  = threadIdx.x;
    const int w    = tid >> 5;
    const int lane = tid & 31;
    const unsigned FULL = 0xffffffffu;

    const int chunk = (blockIdx.x * 8 + w) * ROWS_PER_WARP;  // first row of this warp
    if (chunk >= n) return;

    // W in registers: lane owns feature columns [4*lane, 4*lane+3]
    const float4 Wa = ((const float4*)W)[lane];        // x half
    const float4 Wb = ((const float4*)W)[32 + lane];   // ref half
    const float  bb = bptr[0];

    const float* xlane = x    + (size_t)lane * 4;
    const float* rlane = refm + (size_t)lane * 4;

    // Segment ids for this warp's 32 rows (one coalesced load, lane-resident)
    const int ri    = chunk + lane;
    const int myidx = index[ri < n ? ri : (n - 1)];

    int    cur  = __shfl_sync(FULL, myidx, 0);
    float4 acc  = make_float4(0.f, 0.f, 0.f, 0.f);
    float  esum = 0.f;

    #pragma unroll
    for (int g = 0; g < 8; g++) {
        const int r0 = chunk + 4 * g;
        if (r0 >= n) break;

        float4 xv[4];
        float  p[4];
        #pragma unroll
        for (int k = 0; k < 4; k++) {
            const int r = r0 + k;
            float4 rv = make_float4(0.f, 0.f, 0.f, 0.f);
            xv[k] = rv;
            if (r < n) {
                xv[k] = *(const float4*)(xlane + (size_t)r * D);
                rv    = *(const float4*)(rlane + (size_t)r * D);
            }
            p[k] = xv[k].x * Wa.x + xv[k].y * Wa.y + xv[k].z * Wa.z + xv[k].w * Wa.w
                 + rv.x    * Wb.x + rv.y    * Wb.y + rv.z    * Wb.z + rv.w    * Wb.w;
        }

        // Tree-merge 4-row reduction: 9 shuffles.
        float t0 = __shfl_xor_sync(FULL, p[0], 16);
        float t1 = __shfl_xor_sync(FULL, p[1], 16);
        float q0 = (lane & 16) ? (p[1] + t1) : (p[0] + t0);
        float t2 = __shfl_xor_sync(FULL, p[2], 16);
        float t3 = __shfl_xor_sync(FULL, p[3], 16);
        float q1 = (lane & 16) ? (p[3] + t3) : (p[2] + t2);
        float u0 = __shfl_xor_sync(FULL, q0, 8);
        float u1 = __shfl_xor_sync(FULL, q1, 8);
        float v  = (lane & 8) ? (q1 + u1) : (q0 + u0);
        v += __shfl_xor_sync(FULL, v, 4);
        v += __shfl_xor_sync(FULL, v, 2);
        v += __shfl_xor_sync(FULL, v, 1);
        // Row sums: lane 0 -> row0, 16 -> row1, 8 -> row2, 24 -> row3.

        // softmax shift-invariant + tanh bounded: no segment max needed.
        const float ev = __expf(fast_tanh(v + bb));
        float e[4];
        e[0] = __shfl_sync(FULL, ev, 0);
        e[1] = __shfl_sync(FULL, ev, 16);
        e[2] = __shfl_sync(FULL, ev, 8);
        e[3] = __shfl_sync(FULL, ev, 24);

        #pragma unroll
        for (int k = 0; k < 4; k++) {
            const int r = r0 + k;
            if (r >= n) break;                       // warp-uniform
            const int sk = __shfl_sync(FULL, myidx, 4 * g + k);
            if (sk != cur) {                         // segment boundary: flush
                float* dst = g_num + (size_t)cur * D + lane * 4;
                atomicAdd(dst + 0, acc.x);
                atomicAdd(dst + 1, acc.y);
                atomicAdd(dst + 2, acc.z);
                atomicAdd(dst + 3, acc.w);
                if (lane == 0) atomicAdd(&g_esum[cur], esum);
                acc = make_float4(0.f, 0.f, 0.f, 0.f);
                esum = 0.f;
                cur = sk;
            }
            acc.x += e[k] * xv[k].x;
            acc.y += e[k] * xv[k].y;
            acc.z += e[k] * xv[k].z;
            acc.w += e[k] * xv[k].w;
            esum  += e[k];
        }
    }

    // Final flush
    {
        float* dst = g_num + (size_t)cur * D + lane * 4;
        atomicAdd(dst + 0, acc.x);
        atomicAdd(dst + 1, acc.y);
        atomicAdd(dst + 2, acc.z);
        atomicAdd(dst + 3, acc.w);
        if (lane == 0) atomicAdd(&g_esum[cur], esum);
    }
}

// out[s,:] = num[s,:] / (esum[s] + eps); then re-zero accumulators so the
// next call starts clean (empty segments: 0 / 1e-16 = 0).
__global__ __launch_bounds__(128) void finalize_kernel(float* __restrict__ out)
{
    const int s = blockIdx.x;
    const int t = threadIdx.x;
    const float v  = g_num[(size_t)s * D + t];
    const float es = g_esum[s];
    out[(size_t)s * D + t] = v / (es + 1e-16f);
    g_num[(size_t)s * D + t] = 0.f;
    __syncthreads();
    if (t == 0) g_esum[s] = 0.f;
}

extern "C" void kernel_launch(void* const* d_in, const int* in_sizes, int n_in,
                              void* d_out, int out_size) {
    // metadata order: x, ref, index, batch_size, W, b
    const float* x     = (const float*)d_in[0];
    const float* refm  = (const float*)d_in[1];
    const int*   index = (const int*)  d_in[2];
    const float* W     = (const float*)d_in[4];
    const float* b     = (const float*)d_in[5];
    float* out = (float*)d_out;

    const int n = in_sizes[0] / D;   // 500000
    const int B = out_size / D;      // 16384

    const int rows_per_cta = 8 * ROWS_PER_WARP;              // 256
    const int grid = (n + rows_per_cta - 1) / rows_per_cta;  // 1954

    logits_accum_kernel<<<grid, 256>>>(x, refm, index, W, b, n);
    finalize_kernel<<<B, 128>>>(out);
}

// round 7
// speedup vs baseline: 1.3793x; 1.0634x over previous
#include <cuda_runtime.h>
#include <cuda_bf16.h>

#define D 128
#define B_MAX 16384

// Unnormalized per-segment accumulators. Zero-initialized at load; every
// launch leaves them zeroed again (finalize kernel re-zeroes after reading).
__device__ float g_num[B_MAX * D];   // 8 MB
__device__ float g_esum[B_MAX];

__device__ __forceinline__ float fast_tanh(float v) {
    float r;
    asm("tanh.approx.f32 %0, %1;" : "=f"(r) : "f"(v));
    return r;
}

#define ROWS_PER_WARP 32

__global__ __launch_bounds__(256) void logits_accum_kernel(
    const float* __restrict__ x,
    const float* __restrict__ refm,
    const int*   __restrict__ index,
    const float* __restrict__ W,
    const float* __restrict__ bptr,
    int n)
{
    const int tid  = threadIdx.x;
    const int w    = tid >> 5;
    const int lane = tid & 31;
    const unsigned FULL = 0xffffffffu;

    const int chunk = (blockIdx.x * 8 + w) * ROWS_PER_WARP;  // first row of this warp
    if (chunk >= n) return;
    const bool full = (chunk + ROWS_PER_WARP) <= n;          // warp-uniform fast path

    // W in registers: lane owns feature columns [4*lane, 4*lane+3]
    const float4 Wa = ((const float4*)W)[lane];        // x half
    const float4 Wb = ((const float4*)W)[32 + lane];   // ref half
    const float  bb = bptr[0];

    const float* xlane = x    + (size_t)lane * 4;
    const float* rlane = refm + (size_t)lane * 4;

    // Segment ids for this warp's 32 rows (one coalesced load, lane-resident)
    const int ri    = chunk + lane;
    const int myidx = index[ri < n ? ri : (n - 1)];

    int    cur  = __shfl_sync(FULL, myidx, 0);
    float4 acc  = make_float4(0.f, 0.f, 0.f, 0.f);
    float  esum = 0.f;

    #pragma unroll
    for (int g = 0; g < 8; g++) {
        const int r0 = chunk + 4 * g;
        if (!full && r0 >= n) break;

        float4 xv[4];
        float  p[4];
        #pragma unroll
        for (int k = 0; k < 4; k++) {
            const int r = r0 + k;
            if (full || r < n) {
                xv[k]           = *(const float4*)(xlane + (size_t)r * D);
                const float4 rv = *(const float4*)(rlane + (size_t)r * D);
                p[k] = xv[k].x * Wa.x + xv[k].y * Wa.y + xv[k].z * Wa.z + xv[k].w * Wa.w
                     + rv.x    * Wb.x + rv.y    * Wb.y + rv.z    * Wb.z + rv.w    * Wb.w;
            } else {
                xv[k] = make_float4(0.f, 0.f, 0.f, 0.f);
                p[k]  = 0.f;
            }
        }

        // Tree-merge 4-row reduction: 9 shuffles.
        float t0 = __shfl_xor_sync(FULL, p[0], 16);
        float t1 = __shfl_xor_sync(FULL, p[1], 16);
        float q0 = (lane & 16) ? (p[1] + t1) : (p[0] + t0);
        float t2 = __shfl_xor_sync(FULL, p[2], 16);
        float t3 = __shfl_xor_sync(FULL, p[3], 16);
        float q1 = (lane & 16) ? (p[3] + t3) : (p[2] + t2);
        float u0 = __shfl_xor_sync(FULL, q0, 8);
        float u1 = __shfl_xor_sync(FULL, q1, 8);
        float v  = (lane & 8) ? (q1 + u1) : (q0 + u0);
        v += __shfl_xor_sync(FULL, v, 4);
        v += __shfl_xor_sync(FULL, v, 2);
        v += __shfl_xor_sync(FULL, v, 1);
        // Row sums: lane 0 -> row0, 16 -> row1, 8 -> row2, 24 -> row3.

        // softmax shift-invariant + tanh bounded: no segment max needed.
        const float ev = __expf(fast_tanh(v + bb));
        float e[4];
        e[0] = __shfl_sync(FULL, ev, 0);
        e[1] = __shfl_sync(FULL, ev, 16);
        e[2] = __shfl_sync(FULL, ev, 8);
        e[3] = __shfl_sync(FULL, ev, 24);

        #pragma unroll
        for (int k = 0; k < 4; k++) {
            const int r = r0 + k;
            if (!full && r >= n) break;              // warp-uniform
            const int sk = __shfl_sync(FULL, myidx, 4 * g + k);
            if (sk != cur) {                         // segment boundary: flush
                float* dst = g_num + (size_t)cur * D + lane * 4;
                atomicAdd(dst + 0, acc.x);
                atomicAdd(dst + 1, acc.y);
                atomicAdd(dst + 2, acc.z);
                atomicAdd(dst + 3, acc.w);
                if (lane == 0) atomicAdd(&g_esum[cur], esum);
                acc = make_float4(0.f, 0.f, 0.f, 0.f);
                esum = 0.f;
                cur = sk;
            }
            acc.x += e[k] * xv[k].x;
            acc.y += e[k] * xv[k].y;
            acc.z += e[k] * xv[k].z;
            acc.w += e[k] * xv[k].w;
            esum  += e[k];
        }
    }

    // Final flush
    {
        float* dst = g_num + (size_t)cur * D + lane * 4;
        atomicAdd(dst + 0, acc.x);
        atomicAdd(dst + 1, acc.y);
        atomicAdd(dst + 2, acc.z);
        atomicAdd(dst + 3, acc.w);
        if (lane == 0) atomicAdd(&g_esum[cur], esum);
    }
}

// Warp-per-segment finalize: out[s,:] = num[s,:] / (esum[s]+eps), then re-zero
// the accumulators (self-cleaning for the next launch). All float4 traffic.
__global__ __launch_bounds__(256) void finalize_kernel(float* __restrict__ out)
{
    const int gw   = (blockIdx.x * blockDim.x + threadIdx.x) >> 5;  // segment id
    const int lane = threadIdx.x & 31;

    float4* numv = (float4*)(g_num + (size_t)gw * D);
    const float4 v  = numv[lane];
    const float  es = g_esum[gw];
    const float  inv = 1.0f / (es + 1e-16f);

    ((float4*)(out + (size_t)gw * D))[lane] =
        make_float4(v.x * inv, v.y * inv, v.z * inv, v.w * inv);
    numv[lane] = make_float4(0.f, 0.f, 0.f, 0.f);
    __syncwarp();
    if (lane == 0) g_esum[gw] = 0.f;
}

extern "C" void kernel_launch(void* const* d_in, const int* in_sizes, int n_in,
                              void* d_out, int out_size) {
    // metadata order: x, ref, index, batch_size, W, b
    const float* x     = (const float*)d_in[0];
    const float* refm  = (const float*)d_in[1];
    const int*   index = (const int*)  d_in[2];
    const float* W     = (const float*)d_in[4];
    const float* b     = (const float*)d_in[5];
    float* out = (float*)d_out;

    const int n = in_sizes[0] / D;   // 500000
    const int B = out_size / D;      // 16384

    const int rows_per_cta = 8 * ROWS_PER_WARP;              // 256
    const int grid = (n + rows_per_cta - 1) / rows_per_cta;  // 1954

    logits_accum_kernel<<<grid, 256>>>(x, refm, index, W, b, n);
    finalize_kernel<<<B / 8, 256>>>(out);                    // 8 warps/CTA, warp=segment
}

// round 8
// speedup vs baseline: 1.5178x; 1.1005x over previous
#include <cuda_runtime.h>
#include <cuda_bf16.h>

#define D 128
#define B_MAX 16384

// Unnormalized per-segment accumulators. Zero-initialized at load; every
// launch leaves them zeroed again (finalize kernel re-zeroes after reading).
__device__ float g_num[B_MAX * D];   // 8 MB
__device__ float g_esum[B_MAX];

__device__ __forceinline__ float fast_tanh(float v) {
    float r;
    asm("tanh.approx.f32 %0, %1;" : "=f"(r) : "f"(v));
    return r;
}

// Streaming (evict-first) float4 load: data is touched exactly once.
__device__ __forceinline__ float4 ldcs_f4(const float* p) {
    float4 v;
    asm("ld.global.cs.v4.f32 {%0,%1,%2,%3}, [%4];"
        : "=f"(v.x), "=f"(v.y), "=f"(v.z), "=f"(v.w) : "l"(p));
    return v;
}

#define ROWS_PER_WARP 32

__global__ __launch_bounds__(256) void logits_accum_kernel(
    const float* __restrict__ x,
    const float* __restrict__ refm,
    const int*   __restrict__ index,
    const float* __restrict__ W,
    const float* __restrict__ bptr,
    int n)
{
    const int tid  = threadIdx.x;
    const int w    = tid >> 5;
    const int lane = tid & 31;
    const unsigned FULL = 0xffffffffu;

    const int chunk = (blockIdx.x * 8 + w) * ROWS_PER_WARP;  // first row of this warp
    if (chunk >= n) return;
    const bool full = (chunk + ROWS_PER_WARP) <= n;          // warp-uniform fast path

    // W in registers: lane owns feature columns [4*lane, 4*lane+3]
    const float4 Wa = ((const float4*)W)[lane];        // x half
    const float4 Wb = ((const float4*)W)[32 + lane];   // ref half
    const float  bb = bptr[0];

    const float* xlane = x    + (size_t)lane * 4;
    const float* rlane = refm + (size_t)lane * 4;

    // Segment ids for this warp's 32 rows (one coalesced load, lane-resident)
    const int ri    = chunk + lane;
    const int myidx = index[ri < n ? ri : (n - 1)];

    int    cur  = __shfl_sync(FULL, myidx, 0);
    float4 acc  = make_float4(0.f, 0.f, 0.f, 0.f);
    float  esum = 0.f;

    #pragma unroll
    for (int g = 0; g < 8; g++) {
        const int r0 = chunk + 4 * g;
        if (!full && r0 >= n) break;

        float4 xv[4];
        float  p[4];
        #pragma unroll
        for (int k = 0; k < 4; k++) {
            const int r = r0 + k;
            if (full || r < n) {
                xv[k]           = ldcs_f4(xlane + (size_t)r * D);
                const float4 rv = ldcs_f4(rlane + (size_t)r * D);
                p[k] = xv[k].x * Wa.x + xv[k].y * Wa.y + xv[k].z * Wa.z + xv[k].w * Wa.w
                     + rv.x    * Wb.x + rv.y    * Wb.y + rv.z    * Wb.z + rv.w    * Wb.w;
            } else {
                xv[k] = make_float4(0.f, 0.f, 0.f, 0.f);
                p[k]  = 0.f;
            }
        }

        // Tree-merge 4-row reduction: 9 shuffles.
        float t0 = __shfl_xor_sync(FULL, p[0], 16);
        float t1 = __shfl_xor_sync(FULL, p[1], 16);
        float q0 = (lane & 16) ? (p[1] + t1) : (p[0] + t0);
        float t2 = __shfl_xor_sync(FULL, p[2], 16);
        float t3 = __shfl_xor_sync(FULL, p[3], 16);
        float q1 = (lane & 16) ? (p[3] + t3) : (p[2] + t2);
        float u0 = __shfl_xor_sync(FULL, q0, 8);
        float u1 = __shfl_xor_sync(FULL, q1, 8);
        float v  = (lane & 8) ? (q1 + u1) : (q0 + u0);
        v += __shfl_xor_sync(FULL, v, 4);
        v += __shfl_xor_sync(FULL, v, 2);
        v += __shfl_xor_sync(FULL, v, 1);
        // Row sums: lane 0 -> row0, 16 -> row1, 8 -> row2, 24 -> row3.

        // softmax shift-invariant + tanh bounded: no segment max needed.
        const float ev = __expf(fast_tanh(v + bb));
        float e[4];
        e[0] = __shfl_sync(FULL, ev, 0);
        e[1] = __shfl_sync(FULL, ev, 16);
        e[2] = __shfl_sync(FULL, ev, 8);
        e[3] = __shfl_sync(FULL, ev, 24);

        #pragma unroll
        for (int k = 0; k < 4; k++) {
            const int r = r0 + k;
            if (!full && r >= n) break;              // warp-uniform
            const int sk = __shfl_sync(FULL, myidx, 4 * g + k);
            if (sk != cur) {                         // segment boundary: flush
                float* dst = g_num + (size_t)cur * D + lane * 4;
                atomicAdd(dst + 0, acc.x);
                atomicAdd(dst + 1, acc.y);
                atomicAdd(dst + 2, acc.z);
                atomicAdd(dst + 3, acc.w);
                if (lane == 0) atomicAdd(&g_esum[cur], esum);
                acc = make_float4(0.f, 0.f, 0.f, 0.f);
                esum = 0.f;
                cur = sk;
            }
            acc.x += e[k] * xv[k].x;
            acc.y += e[k] * xv[k].y;
            acc.z += e[k] * xv[k].z;
            acc.w += e[k] * xv[k].w;
            esum  += e[k];
        }
    }

    // Final flush
    {
        float* dst = g_num + (size_t)cur * D + lane * 4;
        atomicAdd(dst + 0, acc.x);
        atomicAdd(dst + 1, acc.y);
        atomicAdd(dst + 2, acc.z);
        atomicAdd(dst + 3, acc.w);
        if (lane == 0) atomicAdd(&g_esum[cur], esum);
    }
}

#define SEGS_PER_WARP 4

// Finalize: each warp handles 4 segments, all loads batched first (MLP=5/warp),
// then divide + write + re-zero. Accumulators are left zeroed for next launch.
__global__ __launch_bounds__(256) void finalize_kernel(float* __restrict__ out)
{
    const int warp0 = ((blockIdx.x * blockDim.x + threadIdx.x) >> 5) * SEGS_PER_WARP;
    const int lane  = threadIdx.x & 31;

    float4 v[SEGS_PER_WARP];
    float  es[SEGS_PER_WARP];

    #pragma unroll
    for (int i = 0; i < SEGS_PER_WARP; i++) {
        v[i] = ((float4*)(g_num + (size_t)(warp0 + i) * D))[lane];
    }
    #pragma unroll
    for (int i = 0; i < SEGS_PER_WARP; i++) {
        es[i] = g_esum[warp0 + i];
    }
    #pragma unroll
    for (int i = 0; i < SEGS_PER_WARP; i++) {
        const int s = warp0 + i;
        const float inv = 1.0f / (es[i] + 1e-16f);
        ((float4*)(out + (size_t)s * D))[lane] =
            make_float4(v[i].x * inv, v[i].y * inv, v[i].z * inv, v[i].w * inv);
        ((float4*)(g_num + (size_t)s * D))[lane] = make_float4(0.f, 0.f, 0.f, 0.f);
    }
    __syncwarp();
    if (lane < SEGS_PER_WARP) g_esum[warp0 + lane] = 0.f;
}

extern "C" void kernel_launch(void* const* d_in, const int* in_sizes, int n_in,
                              void* d_out, int out_size) {
    // metadata order: x, ref, index, batch_size, W, b
    const float* x     = (const float*)d_in[0];
    const float* refm  = (const float*)d_in[1];
    const int*   index = (const int*)  d_in[2];
    const float* W     = (const float*)d_in[4];
    const float* b     = (const float*)d_in[5];
    float* out = (float*)d_out;

    const int n = in_sizes[0] / D;   // 500000
    const int B = out_size / D;      // 16384

    const int rows_per_cta = 8 * ROWS_PER_WARP;              // 256
    const int grid = (n + rows_per_cta - 1) / rows_per_cta;  // 1954

    logits_accum_kernel<<<grid, 256>>>(x, refm, index, W, b, n);
    finalize_kernel<<<B / (8 * SEGS_PER_WARP), 256>>>(out);  // 512 CTAs
}